// round 2
// baseline (speedup 1.0000x reference)
#include <cuda_runtime.h>

#define FFT_L   8192
#define NLAYERS 4
#define NSTATE  64
#define NROWS   4096          // 8 * 512
#define THREADS 512

// ---------------- static device scratch (no allocations allowed) ----------------
__device__ __align__(16) float  g_scratch[(size_t)NROWS * FFT_L];   // 128 MB ping buffer
__device__ __align__(16) float2 g_tw[FFT_L];                        // W_N^k = exp(-2*pi*i*k/N)
__device__ __align__(16) float2 g_ke[NLAYERS][FFT_L];               // Hermitian kernel * (1/N)

// ---------------- complex helpers ----------------
__device__ __forceinline__ float2 cmul(float2 a, float2 b) {
    return make_float2(fmaf(a.x, b.x, -a.y * b.y), fmaf(a.x, b.y, a.y * b.x));
}
__device__ __forceinline__ float2 cadd(float2 a, float2 b) { return make_float2(a.x + b.x, a.y + b.y); }
__device__ __forceinline__ float2 csub(float2 a, float2 b) { return make_float2(a.x - b.x, a.y - b.y); }
// multiply by -i (forward) or +i (inverse)
template <bool INV>
__device__ __forceinline__ float2 mulj(float2 a) {
    return INV ? make_float2(-a.y, a.x) : make_float2(a.y, -a.x);
}

__device__ __forceinline__ float gelu_exact(float v) {
    return 0.5f * v * (1.0f + erff(v * 0.70710678118654752f));
}

// ---------------- twiddle table init ----------------
__global__ void init_tw_kernel() {
    int j = blockIdx.x * blockDim.x + threadIdx.x;
    if (j < FFT_L) {
        float s, c;
        // exp(-2*pi*i*j/N): angle in units of pi is -j/(N/2) (exact in fp32)
        sincospif(-(float)j / (float)(FFT_L / 2), &s, &c);
        g_tw[j] = make_float2(c, s);
    }
}

// ---------------- DPLR generating-function kernel ----------------
__device__ float2 eval_K(int j, const float* lr, const float* li,
                         const float* P, const float* B, const float* Ct, float step) {
    // Omega_j = exp(-2*pi*i*j/L), angle computed in fp32 like the reference
    float ang = (-6.2831855f * (float)j) / 8192.0f;
    float s, c;
    sincosf(ang, &s, &c);
    float opr = 1.0f + c, opi = s;   // 1 + Omega
    float omr = 1.0f - c, omi = -s;  // 1 - Omega
    float inv_p2 = 1.0f / (opr * opr + opi * opi);
    // (1-Om)/(1+Om)
    float qr = (omr * opr + omi * opi) * inv_p2;
    float qi = (omi * opr - omr * opi) * inv_p2;
    float gsc = 2.0f / step;
    float gr = gsc * qr, gi = gsc * qi;
    // c = 2/(1+Om)
    float cr = 2.0f * opr * inv_p2, ci = -2.0f * opi * inv_p2;

    float k00r = 0.f, k00i = 0.f, k01r = 0.f, k01i = 0.f;
    float k10r = 0.f, k10i = 0.f, k11r = 0.f, k11i = 0.f;
#pragma unroll 8
    for (int n = 0; n < NSTATE; n++) {
        float dr = gr - lr[n];
        float di = gi - li[n];
        float inv = 1.0f / (dr * dr + di * di);
        float ir = dr * inv, ii = -di * inv;   // 1/(g - lambda_n)
        float b = B[n], p = P[n], ct = Ct[n];
        float v00 = ct * b, v01 = ct * p, v10 = p * b, v11 = p * p;
        k00r += v00 * ir; k00i += v00 * ii;
        k01r += v01 * ir; k01i += v01 * ii;
        k10r += v10 * ir; k10i += v10 * ii;
        k11r += v11 * ir; k11i += v11 * ii;
    }
    // t = k00 - k01*k10/(1+k11)
    float d1r = 1.0f + k11r, d1i = k11i;
    float invd1 = 1.0f / (d1r * d1r + d1i * d1i);
    float numr = k01r * k10r - k01i * k10i;
    float numi = k01r * k10i + k01i * k10r;
    float qr2 = (numr * d1r + numi * d1i) * invd1;
    float qi2 = (numi * d1r - numr * d1i) * invd1;
    float tr = k00r - qr2, ti = k00i - qi2;
    return make_float2(cr * tr - ci * ti, cr * ti + ci * tr);
}

__global__ void compute_ke_kernel(const float* __restrict__ Lr, const float* __restrict__ Li,
                                  const float* __restrict__ P,  const float* __restrict__ B,
                                  const float* __restrict__ Ct, const float* __restrict__ step) {
    int gid = blockIdx.x * blockDim.x + threadIdx.x;
    if (gid >= NLAYERS * FFT_L) return;
    int layer = gid >> 13;
    int j     = gid & (FFT_L - 1);
    const float* lr = Lr + layer * NSTATE;
    const float* li = Li + layer * NSTATE;
    const float* p  = P  + layer * NSTATE;
    const float* b  = B  + layer * NSTATE;
    const float* ct = Ct + layer * NSTATE;
    float st = step[layer];

    float2 K1 = eval_K(j, lr, li, p, b, ct, st);
    float2 K2 = eval_K((FFT_L - j) & (FFT_L - 1), lr, li, p, b, ct, st);
    // Hermitian part (the anti-Hermitian part only affects the discarded Im output),
    // scaled by 1/N for the inverse FFT.
    const float sc = 0.5f / (float)FFT_L;
    g_ke[layer][j] = make_float2((K1.x + K2.x) * sc, (K1.y - K2.y) * sc);
}

// ---------------- Stockham FFT stages (shared memory, ping-pong) ----------------
// Radix-8 stage at state (n = N>>T, s = 2^T):
//   y[q + s*(8p+k)] = W_n^{p*k} * sum_j x[q + s*p + 1024*j] * W8^{j*k}
template <bool INV, int T>
__device__ __forceinline__ void r8_stage(const float2* __restrict__ src,
                                         float2* __restrict__ dst) {
    const float CC = 0.70710678118654752f;
#pragma unroll
    for (int it = 0; it < 1024 / THREADS; ++it) {
        int idx = threadIdx.x + it * THREADS;     // 0..1023
        int p = idx >> T;
        int q = idx & ((1 << T) - 1);
        const float2* sp = src + q + (p << T);
        float2 a0 = sp[0 * 1024], a1 = sp[1 * 1024], a2 = sp[2 * 1024], a3 = sp[3 * 1024];
        float2 a4 = sp[4 * 1024], a5 = sp[5 * 1024], a6 = sp[6 * 1024], a7 = sp[7 * 1024];

        // DFT-8 (DIT within the butterfly)
        float2 s0 = cadd(a0, a4), s1 = csub(a0, a4);
        float2 s2 = cadd(a2, a6), s3 = mulj<INV>(csub(a2, a6));
        float2 E0 = cadd(s0, s2), E2 = csub(s0, s2);
        float2 E1 = cadd(s1, s3), E3 = csub(s1, s3);
        float2 t0 = cadd(a1, a5), t1 = csub(a1, a5);
        float2 t2 = cadd(a3, a7), t3 = mulj<INV>(csub(a3, a7));
        float2 O0 = cadd(t0, t2), O2 = csub(t0, t2);
        float2 O1 = cadd(t1, t3), O3 = csub(t1, t3);

        float2 O1w = INV ? make_float2(CC * (O1.x - O1.y), CC * (O1.x + O1.y))
                         : make_float2(CC * (O1.x + O1.y), CC * (O1.y - O1.x));
        float2 O2w = mulj<INV>(O2);
        float2 O3w = INV ? make_float2(-CC * (O3.x + O3.y), CC * (O3.x - O3.y))
                         : make_float2(CC * (O3.y - O3.x), -CC * (O3.x + O3.y));

        float2 X0 = cadd(E0, O0),  X4 = csub(E0, O0);
        float2 X1 = cadd(E1, O1w), X5 = csub(E1, O1w);
        float2 X2 = cadd(E2, O2w), X6 = csub(E2, O2w);
        float2 X3 = cadd(E3, O3w), X7 = csub(E3, O3w);

        // twiddles W_n^{p*k} = W_N^{(p<<T)*k}, built from one table load
        float2 w1 = g_tw[p << T];
        if (INV) w1.y = -w1.y;
        float2 w2 = cmul(w1, w1);
        float2 w3 = cmul(w2, w1);
        float2 w4 = cmul(w2, w2);
        float2 w5 = cmul(w4, w1);
        float2 w6 = cmul(w3, w3);
        float2 w7 = cmul(w4, w3);

        float2* d = dst + q + (p << (T + 3));
        d[0 << T] = X0;
        d[1 << T] = cmul(X1, w1);
        d[2 << T] = cmul(X2, w2);
        d[3 << T] = cmul(X3, w3);
        d[4 << T] = cmul(X4, w4);
        d[5 << T] = cmul(X5, w5);
        d[6 << T] = cmul(X6, w6);
        d[7 << T] = cmul(X7, w7);
    }
}

// Final radix-2 stage: (n=2, s=4096, m=1); no twiddles.
__device__ __forceinline__ void r2_stage(const float2* __restrict__ src,
                                         float2* __restrict__ dst) {
#pragma unroll
    for (int it = 0; it < 4096 / THREADS; ++it) {
        int q = threadIdx.x + it * THREADS;
        float2 a = src[q], b = src[q + 4096];
        dst[q]        = cadd(a, b);
        dst[q + 4096] = csub(a, b);
    }
}

// ---------------- fused per-layer kernel: FFT -> filter -> IFFT -> residual+GELU ----------------
__global__ void __launch_bounds__(THREADS, 1)
ssm_layer_kernel(const float* __restrict__ in, float* __restrict__ out, int layer) {
    extern __shared__ float2 smem[];
    float2* X = smem;              // 8192
    float2* Y = smem + FFT_L;      // 8192
    float2* U = smem + 2 * FFT_L;  // residual stash (row0, row1)

    size_t row = (size_t)blockIdx.x * 2;
    const float* in0 = in + row * FFT_L;
    const float* in1 = in + (row + 1) * FFT_L;

#pragma unroll
    for (int it = 0; it < FFT_L / THREADS; ++it) {
        int i = threadIdx.x + it * THREADS;
        float2 v = make_float2(in0[i], in1[i]);   // pack two real rows as one complex seq
        X[i] = v;
        U[i] = v;
    }
    __syncthreads();

    // forward FFT: X -> Y -> X -> Y -> X -> Y
    r8_stage<false, 0>(X, Y); __syncthreads();
    r8_stage<false, 3>(Y, X); __syncthreads();
    r8_stage<false, 6>(X, Y); __syncthreads();
    r8_stage<false, 9>(Y, X); __syncthreads();
    r2_stage(X, Y);           __syncthreads();

    // pointwise Hermitian filter (includes 1/N)
    const float2* __restrict__ ke = g_ke[layer];
#pragma unroll
    for (int it = 0; it < FFT_L / THREADS; ++it) {
        int i = threadIdx.x + it * THREADS;
        Y[i] = cmul(Y[i], ke[i]);
    }
    __syncthreads();

    // inverse FFT (conjugate twiddles): Y -> X -> Y -> X -> Y -> X
    r8_stage<true, 0>(Y, X); __syncthreads();
    r8_stage<true, 3>(X, Y); __syncthreads();
    r8_stage<true, 6>(Y, X); __syncthreads();
    r8_stage<true, 9>(X, Y); __syncthreads();
    r2_stage(Y, X);          __syncthreads();

    float* o0 = out + row * FFT_L;
    float* o1 = out + (row + 1) * FFT_L;
#pragma unroll
    for (int it = 0; it < FFT_L / THREADS; ++it) {
        int i = threadIdx.x + it * THREADS;
        float2 w = X[i];
        float2 u = U[i];
        o0[i] = gelu_exact(w.x + u.x);
        o1[i] = gelu_exact(w.y + u.y);
    }
}

// ---------------- launch ----------------
extern "C" void kernel_launch(void* const* d_in, const int* in_sizes, int n_in,
                              void* d_out, int out_size) {
    const float* u  = (const float*)d_in[0];
    const float* Lr = (const float*)d_in[1];
    const float* Li = (const float*)d_in[2];
    const float* P  = (const float*)d_in[3];
    const float* B  = (const float*)d_in[4];
    const float* Ct = (const float*)d_in[5];
    const float* st = (const float*)d_in[6];
    float* out = (float*)d_out;

    float* scratch = nullptr;
    cudaGetSymbolAddress((void**)&scratch, g_scratch);

    const size_t smem_bytes = 3 * FFT_L * sizeof(float2);   // 192 KB
    cudaFuncSetAttribute(ssm_layer_kernel,
                         cudaFuncAttributeMaxDynamicSharedMemorySize, (int)smem_bytes);

    init_tw_kernel<<<FFT_L / 256, 256>>>();
    compute_ke_kernel<<<(NLAYERS * FFT_L) / 256, 256>>>(Lr, Li, P, B, Ct, st);

    ssm_layer_kernel<<<NROWS / 2, THREADS, smem_bytes>>>(u,       scratch, 0);
    ssm_layer_kernel<<<NROWS / 2, THREADS, smem_bytes>>>(scratch, out,     1);
    ssm_layer_kernel<<<NROWS / 2, THREADS, smem_bytes>>>(out,     scratch, 2);
    ssm_layer_kernel<<<NROWS / 2, THREADS, smem_bytes>>>(scratch, out,     3);
}

// round 3
// speedup vs baseline: 1.3128x; 1.3128x over previous
#include <cuda_runtime.h>

#define FFT_L   8192
#define NLAYERS 4
#define NSTATE  64
#define NROWS   4096
#define THREADS 512

// ---------------- static device scratch ----------------
__device__ __align__(16) float  g_scratch[(size_t)NROWS * FFT_L];   // 128 MB ping buffer
__device__ __align__(16) float2 g_tw[FFT_L];                        // W_N^k
__device__ __align__(16) float2 g_kraw[NLAYERS][FFT_L];             // raw K(omega_j)
__device__ __align__(16) float2 g_ke[NLAYERS][FFT_L];               // Hermitian kernel * (1/N)

// ---------------- complex helpers ----------------
__device__ __forceinline__ float2 cmul(float2 a, float2 b) {
    return make_float2(fmaf(a.x, b.x, -a.y * b.y), fmaf(a.x, b.y, a.y * b.x));
}
__device__ __forceinline__ float2 cadd(float2 a, float2 b) { return make_float2(a.x + b.x, a.y + b.y); }
__device__ __forceinline__ float2 csub(float2 a, float2 b) { return make_float2(a.x - b.x, a.y - b.y); }
template <bool INV>
__device__ __forceinline__ float2 mulj(float2 a) {   // * (-i) fwd, * (+i) inv
    return INV ? make_float2(-a.y, a.x) : make_float2(a.y, -a.x);
}
__device__ __forceinline__ float gelu_exact(float v) {
    return 0.5f * v * (1.0f + erff(v * 0.70710678118654752f));
}
// bank-conflict-free smem swizzle (bijective, modifies bits 0-3 only)
__device__ __forceinline__ int sw(int i) { return i ^ ((i >> 3) & 15); }

// ---------------- DFT-8 / DFT-16 in registers ----------------
template <bool INV>
__device__ __forceinline__ void dft8(float2 a[8]) {
    const float CC = 0.70710678118654752f;
    float2 s0 = cadd(a[0], a[4]), s1 = csub(a[0], a[4]);
    float2 s2 = cadd(a[2], a[6]), s3 = mulj<INV>(csub(a[2], a[6]));
    float2 E0 = cadd(s0, s2), E2 = csub(s0, s2);
    float2 E1 = cadd(s1, s3), E3 = csub(s1, s3);
    float2 t0 = cadd(a[1], a[5]), t1 = csub(a[1], a[5]);
    float2 t2 = cadd(a[3], a[7]), t3 = mulj<INV>(csub(a[3], a[7]));
    float2 O0 = cadd(t0, t2), O2 = csub(t0, t2);
    float2 O1 = cadd(t1, t3), O3 = csub(t1, t3);
    float2 O1w = INV ? make_float2(CC * (O1.x - O1.y), CC * (O1.x + O1.y))
                     : make_float2(CC * (O1.x + O1.y), CC * (O1.y - O1.x));
    float2 O2w = mulj<INV>(O2);
    float2 O3w = INV ? make_float2(-CC * (O3.x + O3.y), CC * (O3.x - O3.y))
                     : make_float2(CC * (O3.y - O3.x), -CC * (O3.x + O3.y));
    a[0] = cadd(E0, O0);  a[4] = csub(E0, O0);
    a[1] = cadd(E1, O1w); a[5] = csub(E1, O1w);
    a[2] = cadd(E2, O2w); a[6] = csub(E2, O2w);
    a[3] = cadd(E3, O3w); a[7] = csub(E3, O3w);
}

template <bool INV>
__device__ __forceinline__ void dft16(const float2 a[16], float2 X[16]) {
    float2 E[8] = {a[0], a[2], a[4], a[6], a[8], a[10], a[12], a[14]};
    float2 O[8] = {a[1], a[3], a[5], a[7], a[9], a[11], a[13], a[15]};
    dft8<INV>(E);
    dft8<INV>(O);
    const float c1 = 0.9238795325112867f, s1 = 0.3826834323650898f,
                SQ = 0.7071067811865476f;
    const float sg = INV ? 1.0f : -1.0f;
    float2 W[8];
    W[0] = make_float2(1.f, 0.f);
    W[1] = make_float2(c1, sg * s1);
    W[2] = make_float2(SQ, sg * SQ);
    W[3] = make_float2(s1, sg * c1);
    W[4] = make_float2(0.f, sg);
    W[5] = make_float2(-s1, sg * c1);
    W[6] = make_float2(-SQ, sg * SQ);
    W[7] = make_float2(-c1, sg * s1);
#pragma unroll
    for (int k = 0; k < 8; ++k) {
        float2 t = cmul(O[k], W[k]);
        X[k]     = cadd(E[k], t);
        X[k + 8] = csub(E[k], t);
    }
}

// ---------------- prologue kernels ----------------
__global__ void init_tw_kernel() {
    int j = blockIdx.x * blockDim.x + threadIdx.x;
    if (j < FFT_L) {
        float s, c;
        sincospif(-(float)j / (float)(FFT_L / 2), &s, &c);
        g_tw[j] = make_float2(c, s);
    }
}

__global__ void compute_k_kernel(const float* __restrict__ Lr, const float* __restrict__ Li,
                                 const float* __restrict__ P,  const float* __restrict__ B,
                                 const float* __restrict__ Ct, const float* __restrict__ step) {
    int gid = blockIdx.x * blockDim.x + threadIdx.x;
    if (gid >= NLAYERS * FFT_L) return;
    int layer = gid >> 13;
    int j     = gid & (FFT_L - 1);
    const float* lr = Lr + layer * NSTATE;
    const float* li = Li + layer * NSTATE;
    const float* Pp = P  + layer * NSTATE;
    const float* Bp = B  + layer * NSTATE;
    const float* Cp = Ct + layer * NSTATE;
    float st = step[layer];

    float ang = (-6.2831855f * (float)j) / 8192.0f;
    float s, c;
    sincosf(ang, &s, &c);
    float opr = 1.0f + c, opi = s;
    float omr = 1.0f - c, omi = -s;
    float inv_p2 = 1.0f / (opr * opr + opi * opi);
    float qr = (omr * opr + omi * opi) * inv_p2;
    float qi = (omi * opr - omr * opi) * inv_p2;
    float gsc = 2.0f / st;
    float gr = gsc * qr, gi = gsc * qi;
    float cr = 2.0f * opr * inv_p2, ci = -2.0f * opi * inv_p2;

    float k00r = 0.f, k00i = 0.f, k01r = 0.f, k01i = 0.f;
    float k10r = 0.f, k10i = 0.f, k11r = 0.f, k11i = 0.f;
#pragma unroll 8
    for (int n = 0; n < NSTATE; n++) {
        float dr = gr - lr[n];
        float di = gi - li[n];
        float inv = 1.0f / (dr * dr + di * di);
        float ir = dr * inv, ii = -di * inv;
        float b = Bp[n], p = Pp[n], ct = Cp[n];
        float v00 = ct * b, v01 = ct * p, v10 = p * b, v11 = p * p;
        k00r += v00 * ir; k00i += v00 * ii;
        k01r += v01 * ir; k01i += v01 * ii;
        k10r += v10 * ir; k10i += v10 * ii;
        k11r += v11 * ir; k11i += v11 * ii;
    }
    float d1r = 1.0f + k11r, d1i = k11i;
    float invd1 = 1.0f / (d1r * d1r + d1i * d1i);
    float numr = k01r * k10r - k01i * k10i;
    float numi = k01r * k10i + k01i * k10r;
    float qr2 = (numr * d1r + numi * d1i) * invd1;
    float qi2 = (numi * d1r - numr * d1i) * invd1;
    float tr = k00r - qr2, ti = k00i - qi2;
    g_kraw[layer][j] = make_float2(cr * tr - ci * ti, cr * ti + ci * tr);
}

__global__ void symmetrize_k_kernel() {
    int gid = blockIdx.x * blockDim.x + threadIdx.x;
    if (gid >= NLAYERS * FFT_L) return;
    int layer = gid >> 13;
    int j     = gid & (FFT_L - 1);
    float2 K1 = g_kraw[layer][j];
    float2 K2 = g_kraw[layer][(FFT_L - j) & (FFT_L - 1)];
    const float sc = 0.5f / (float)FFT_L;   // Hermitian part * 1/N
    g_ke[layer][j] = make_float2((K1.x + K2.x) * sc, (K1.y - K2.y) * sc);
}

// ---------------- radix-8 pass (generic, swizzled smem) ----------------
template <bool INV, int T>
__device__ __forceinline__ void r8_pass(const float2* __restrict__ src,
                                        float2* __restrict__ dst) {
#pragma unroll
    for (int it = 0; it < 1024 / THREADS; ++it) {
        int idx = threadIdx.x + it * THREADS;
        float2 a[8];
#pragma unroll
        for (int j = 0; j < 8; ++j) a[j] = src[sw(idx + 1024 * j)];
        dft8<INV>(a);
        int pT = idx & ~((1 << T) - 1);
        int q  = idx & ((1 << T) - 1);
        float2 w1 = g_tw[pT];
        if (INV) w1.y = -w1.y;
        float2 w2 = cmul(w1, w1), w3 = cmul(w2, w1), w4 = cmul(w2, w2);
        float2 w5 = cmul(w4, w1), w6 = cmul(w3, w3), w7 = cmul(w4, w3);
        int dbase = q + (pT << 3);
        dst[sw(dbase + (0 << T))] = a[0];
        dst[sw(dbase + (1 << T))] = cmul(a[1], w1);
        dst[sw(dbase + (2 << T))] = cmul(a[2], w2);
        dst[sw(dbase + (3 << T))] = cmul(a[3], w3);
        dst[sw(dbase + (4 << T))] = cmul(a[4], w4);
        dst[sw(dbase + (5 << T))] = cmul(a[5], w5);
        dst[sw(dbase + (6 << T))] = cmul(a[6], w6);
        dst[sw(dbase + (7 << T))] = cmul(a[7], w7);
    }
}

// ---------------- fused per-layer kernel ----------------
__global__ void __launch_bounds__(THREADS, 1)
ssm_layer_kernel(const float* __restrict__ in, float* __restrict__ out, int layer) {
    extern __shared__ float2 smem[];
    float2* X = smem;              // swizzled
    float2* Y = smem + FFT_L;      // swizzled
    float2* U = smem + 2 * FFT_L;  // plain residual stash

    size_t row = (size_t)blockIdx.x * 2;
    const float* in0 = in + row * FFT_L;
    const float* in1 = in + (row + 1) * FFT_L;

    // ---- F1: radix-8 (T=0) reading straight from gmem; stash residual ----
#pragma unroll
    for (int it = 0; it < 1024 / THREADS; ++it) {
        int idx = threadIdx.x + it * THREADS;
        float2 a[8];
#pragma unroll
        for (int j = 0; j < 8; ++j) {
            int i = idx + 1024 * j;
            float2 v = make_float2(in0[i], in1[i]);
            U[i] = v;
            a[j] = v;
        }
        dft8<false>(a);
        float2 w1 = g_tw[idx];
        float2 w2 = cmul(w1, w1), w3 = cmul(w2, w1), w4 = cmul(w2, w2);
        float2 w5 = cmul(w4, w1), w6 = cmul(w3, w3), w7 = cmul(w4, w3);
        int dbase = idx << 3;
        X[sw(dbase + 0)] = a[0];
        X[sw(dbase + 1)] = cmul(a[1], w1);
        X[sw(dbase + 2)] = cmul(a[2], w2);
        X[sw(dbase + 3)] = cmul(a[3], w3);
        X[sw(dbase + 4)] = cmul(a[4], w4);
        X[sw(dbase + 5)] = cmul(a[5], w5);
        X[sw(dbase + 6)] = cmul(a[6], w6);
        X[sw(dbase + 7)] = cmul(a[7], w7);
    }
    __syncthreads();

    r8_pass<false, 3>(X, Y); __syncthreads();
    r8_pass<false, 6>(Y, X); __syncthreads();

    // ---- F4: final radix-16 in registers, filter fused into store ----
    {
        const float2* __restrict__ ke = g_ke[layer];
        int q = threadIdx.x;
        float2 a[16], Xo[16];
#pragma unroll
        for (int j = 0; j < 16; ++j) a[j] = X[sw(q + 512 * j)];
        dft16<false>(a, Xo);
#pragma unroll
        for (int k = 0; k < 16; ++k) {
            int i = q + 512 * k;
            Y[sw(i)] = cmul(Xo[k], ke[i]);
        }
    }
    __syncthreads();

    // ---- inverse FFT ----
    r8_pass<true, 0>(Y, X); __syncthreads();
    r8_pass<true, 3>(X, Y); __syncthreads();
    r8_pass<true, 6>(Y, X); __syncthreads();

    // ---- I4: final radix-16 + residual + GELU, straight to gmem ----
    {
        float* o0 = out + row * FFT_L;
        float* o1 = out + (row + 1) * FFT_L;
        int q = threadIdx.x;
        float2 a[16], Xo[16];
#pragma unroll
        for (int j = 0; j < 16; ++j) a[j] = X[sw(q + 512 * j)];
        dft16<true>(a, Xo);
#pragma unroll
        for (int k = 0; k < 16; ++k) {
            int i = q + 512 * k;
            float2 u = U[i];
            o0[i] = gelu_exact(Xo[k].x + u.x);
            o1[i] = gelu_exact(Xo[k].y + u.y);
        }
    }
}

// ---------------- launch ----------------
extern "C" void kernel_launch(void* const* d_in, const int* in_sizes, int n_in,
                              void* d_out, int out_size) {
    const float* u  = (const float*)d_in[0];
    const float* Lr = (const float*)d_in[1];
    const float* Li = (const float*)d_in[2];
    const float* P  = (const float*)d_in[3];
    const float* B  = (const float*)d_in[4];
    const float* Ct = (const float*)d_in[5];
    const float* st = (const float*)d_in[6];
    float* out = (float*)d_out;

    float* scratch = nullptr;
    cudaGetSymbolAddress((void**)&scratch, g_scratch);

    const size_t smem_bytes = 3 * FFT_L * sizeof(float2);   // 192 KB
    cudaFuncSetAttribute(ssm_layer_kernel,
                         cudaFuncAttributeMaxDynamicSharedMemorySize, (int)smem_bytes);

    init_tw_kernel<<<FFT_L / 256, 256>>>();
    compute_k_kernel<<<(NLAYERS * FFT_L) / 256, 256>>>(Lr, Li, P, B, Ct, st);
    symmetrize_k_kernel<<<(NLAYERS * FFT_L) / 256, 256>>>();

    ssm_layer_kernel<<<NROWS / 2, THREADS, smem_bytes>>>(u,       scratch, 0);
    ssm_layer_kernel<<<NROWS / 2, THREADS, smem_bytes>>>(scratch, out,     1);
    ssm_layer_kernel<<<NROWS / 2, THREADS, smem_bytes>>>(out,     scratch, 2);
    ssm_layer_kernel<<<NROWS / 2, THREADS, smem_bytes>>>(scratch, out,     3);
}